// round 5
// baseline (speedup 1.0000x reference)
#include <cuda_runtime.h>
#include <cstdint>

// ---------------------------------------------------------------------------
// SetAbstraction (PointNet++): FPS -> ball query -> MLP -> max
// B=2, N=16384, S=4096, K=32, F_IN=16, hidden 64-64-128
// Round 5 FPS: 1024 threads, two lanes per cell (interleaved halves), keys in
// registers, ONE warp argmax per iteration (not per cell), depth-1 prefetch.
// Selection sequence bit-identical to the naive scan.
// ---------------------------------------------------------------------------

#define BB   2
#define NN   16384
#define SS   4096
#define KK   32
#define FIN  16
#define HOUT 128
#define GC    8
#define NCELL 512
#define CW    0.125f
#define FULLM 0xffffffffu

// ---- scratch (__device__ globals; no allocation allowed) -------------------
__device__ float g_centers[BB * SS * 3];
__device__ int   g_nbr[BB * SS * KK];
__device__ int   g_cnt[BB * SS];

__device__ float2 g_sxy[BB * NN];      // sorted (x,y)
__device__ int2   g_szi[BB * NN];      // sorted (z bits, orig idx)
__device__ int    g_hist[BB * NCELL];
__device__ int    g_cstart[BB * (NCELL + 1)];
__device__ int    g_fill[BB * NCELL];

__device__ __forceinline__ int cell_of(float x, float y, float z) {
    int ix = (int)(x * (float)GC); ix = ix < 0 ? 0 : (ix > GC - 1 ? GC - 1 : ix);
    int iy = (int)(y * (float)GC); iy = iy < 0 ? 0 : (iy > GC - 1 ? GC - 1 : iy);
    int iz = (int)(z * (float)GC); iz = iz < 0 ? 0 : (iz > GC - 1 ? GC - 1 : iz);
    return (iz * GC + iy) * GC + ix;
}

// ===========================================================================
// Preprocessing: histogram -> scan -> scatter (counting sort by cell)
// ===========================================================================
__global__ void init_hist_kernel() {
    int i = blockIdx.x * blockDim.x + threadIdx.x;
    if (i < BB * NCELL) g_hist[i] = 0;
}

__global__ void cell_count_kernel(const float* __restrict__ pos) {
    int i = blockIdx.x * blockDim.x + threadIdx.x;
    if (i >= BB * NN) return;
    int b = i >> 14;
    float x = pos[(size_t)i * 3 + 0], y = pos[(size_t)i * 3 + 1], z = pos[(size_t)i * 3 + 2];
    atomicAdd(&g_hist[b * NCELL + cell_of(x, y, z)], 1);
}

__global__ void cell_scan_kernel() {
    __shared__ int sh[NCELL];
    __shared__ int ss[NCELL + 1];
    int b = blockIdx.x, tid = threadIdx.x;
    if (tid < NCELL) sh[tid] = g_hist[b * NCELL + tid];
    __syncthreads();
    if (tid == 0) {
        int acc = 0;
        for (int c = 0; c < NCELL; c++) { ss[c] = acc; acc += sh[c]; }
        ss[NCELL] = acc;
    }
    __syncthreads();
    if (tid < NCELL) {
        g_cstart[b * (NCELL + 1) + tid] = ss[tid];
        g_fill[b * NCELL + tid] = ss[tid];
    }
    if (tid == 0) g_cstart[b * (NCELL + 1) + NCELL] = ss[NCELL];
}

__global__ void cell_scatter_kernel(const float* __restrict__ pos) {
    int i = blockIdx.x * blockDim.x + threadIdx.x;
    if (i >= BB * NN) return;
    int b = i >> 14;
    int li = i & (NN - 1);
    float x = pos[(size_t)i * 3 + 0], y = pos[(size_t)i * 3 + 1], z = pos[(size_t)i * 3 + 2];
    int c = cell_of(x, y, z);
    int p = atomicAdd(&g_fill[b * NCELL + c], 1);
    g_sxy[b * NN + p] = make_float2(x, y);
    g_szi[b * NN + p] = make_int2(__float_as_int(z), li);
}

// ===========================================================================
// Kernel 1: grid-pruned exact FPS. One block per batch, 1024 threads (32 warps).
// Warp w owns cells [16w, 16w+16); lanes l and l^16 co-own cell 16w+(l&15)
// and scan interleaved halves. Keys (max dmin, ~origidx, pos, z) in registers.
// ONE warp argmax per iteration. smem: sorted (x,y) 128KB + dmin 64KB.
// ===========================================================================
__global__ void __launch_bounds__(1024, 1)
fps_kernel(const float* __restrict__ pos, float* __restrict__ out_centers)
{
    extern __shared__ float sm[];
    float2* s_xy   = (float2*)sm;        // NN float2 (128 KB)
    float*  s_dmin = sm + 2 * NN;        // NN floats (64 KB)

    __shared__ unsigned s_rv[32], s_rlo[32];
    __shared__ int      s_rp[32];
    __shared__ float    s_rz[32];
    __shared__ float    s_c[3];

    const int b = blockIdx.x, tid = threadIdx.x;
    const int w = tid >> 5, lane = tid & 31;
    const int half = lane >> 4;
    const int base = b * NN;

    for (int p = tid; p < NN; p += 1024) {
        s_xy[p] = g_sxy[base + p];
        s_dmin[p] = 1e10f;
    }

    // this lane's co-owned cell
    const int cell = (w << 4) + (lane & 15);
    const int cs0 = g_cstart[b * (NCELL + 1) + cell];
    const int cs1 = g_cstart[b * (NCELL + 1) + cell + 1];
    const int ix = cell & 7, iy = (cell >> 3) & 7, iz = cell >> 6;
    const float bcx = ((float)ix + 0.5f) * CW;
    const float bcy = ((float)iy + 0.5f) * CW;
    const float bcz = ((float)iz + 0.5f) * CW;
    const float hw  = 0.5f * CW + 1e-5f;

    unsigned kv = __float_as_uint(1e10f);  // cell key: max dmin (u32 bits, >=0)
    unsigned klo = 0u;                     // ~origidx of winner
    int      kp = 0;                       // winner sorted pos
    float    kz = 0.f;                     // winner z

    if (tid == 0) {
        float cx = pos[(size_t)base * 3 + 0];
        float cy = pos[(size_t)base * 3 + 1];
        float cz = pos[(size_t)base * 3 + 2];
        s_c[0] = cx; s_c[1] = cy; s_c[2] = cz;
        int row = b * SS;
        out_centers[row * 3 + 0] = cx; out_centers[row * 3 + 1] = cy; out_centers[row * 3 + 2] = cz;
        g_centers[row * 3 + 0]   = cx; g_centers[row * 3 + 1]   = cy; g_centers[row * 3 + 2]   = cz;
    }
    __syncthreads();

    for (int t = 1; t < SS; t++) {
        const float cx = s_c[0], cy = s_c[1], cz = s_c[2];

        // --- prune: pair-identical lower bound vs cached cell max ---------
        float pdx = fmaxf(fabsf(cx - bcx) - hw, 0.f);
        float pdy = fmaxf(fabsf(cy - bcy) - hw, 0.f);
        float pdz = fmaxf(fabsf(cz - bcz) - hw, 0.f);
        float lb  = (pdx * pdx + pdy * pdy + pdz * pdz) * 0.999f;
        bool touched = lb < __uint_as_float(kv);

        if (__any_sync(FULLM, touched)) {
            unsigned bu = 0u, blo = 0u; int bp = 0; float bz = 0.f;
            if (touched) {
                int p = cs0 + half;
                int2 zi = make_int2(0, 0); float2 xy = make_float2(0.f, 0.f);
                if (p < cs1) { zi = g_szi[base + p]; xy = s_xy[p]; }
                while (p < cs1) {
                    int pn = p + 2;
                    int2 zin = make_int2(0, 0); float2 xyn = make_float2(0.f, 0.f);
                    if (pn < cs1) { zin = g_szi[base + pn]; xyn = s_xy[pn]; }
                    float zz  = __int_as_float(zi.x);
                    float ddx = __fsub_rn(xy.x, cx);
                    float ddy = __fsub_rn(xy.y, cy);
                    float ddz = __fsub_rn(zz,   cz);
                    float d   = __fadd_rn(__fadd_rn(__fmul_rn(ddx, ddx), __fmul_rn(ddy, ddy)),
                                          __fmul_rn(ddz, ddz));
                    float dm  = fminf(s_dmin[p], d);
                    s_dmin[p] = dm;
                    unsigned du = __float_as_uint(dm);
                    unsigned lo = ~(unsigned)zi.y;
                    if (du > bu || (du == bu && lo > blo)) { bu = du; blo = lo; bp = p; bz = zz; }
                    p = pn; zi = zin; xy = xyn;
                }
            }
            // pair combine: lanes l and l^16 co-own the cell
            unsigned obu  = __shfl_xor_sync(FULLM, bu,  16);
            unsigned oblo = __shfl_xor_sync(FULLM, blo, 16);
            int      obp  = __shfl_xor_sync(FULLM, bp,  16);
            float    obz  = __shfl_xor_sync(FULLM, bz,  16);
            if (obu > bu || (obu == bu && oblo > blo)) { bu = obu; blo = oblo; bp = obp; bz = obz; }
            if (touched) { kv = bu; klo = blo; kp = bp; kz = bz; }

            // warp partial over 32 lanes (16 cells, duplicated keys harmless)
            unsigned mv   = __reduce_max_sync(FULLM, kv);
            unsigned cand = (kv == mv) ? klo : 0u;
            unsigned mlo  = __reduce_max_sync(FULLM, cand);
            unsigned bm   = __ballot_sync(FULLM, (kv == mv) && (cand == mlo));
            if (lane == __ffs(bm) - 1) { s_rv[w] = mv; s_rlo[w] = mlo; s_rp[w] = kp; s_rz[w] = kz; }
        }
        __syncthreads();

        // --- warp 0: final argmax over 32 partials, publish center --------
        if (w == 0) {
            unsigned v   = s_rv[lane];
            unsigned lo2 = s_rlo[lane];
            int      p2  = s_rp[lane];
            float    z2  = s_rz[lane];
            unsigned mv   = __reduce_max_sync(FULLM, v);
            unsigned cand = (v == mv) ? lo2 : 0u;
            unsigned mlo  = __reduce_max_sync(FULLM, cand);
            unsigned bm   = __ballot_sync(FULLM, (v == mv) && (cand == mlo));
            if (lane == __ffs(bm) - 1) {
                float2 xyw = s_xy[p2];
                s_c[0] = xyw.x; s_c[1] = xyw.y; s_c[2] = z2;
                int row = b * SS + t;
                out_centers[row * 3 + 0] = xyw.x; out_centers[row * 3 + 1] = xyw.y; out_centers[row * 3 + 2] = z2;
                g_centers[row * 3 + 0]   = xyw.x; g_centers[row * 3 + 1]   = xyw.y; g_centers[row * 3 + 2]   = z2;
            }
        }
        __syncthreads();
    }
}

// ===========================================================================
// Kernel 2: Ball query — one warp per center; ordered scan, first K within R.
// ===========================================================================
__global__ void __launch_bounds__(256, 8)
ballq_kernel(const float* __restrict__ pos, float* __restrict__ out_batch)
{
    const int w    = (blockIdx.x * blockDim.x + threadIdx.x) >> 5;
    const int lane = threadIdx.x & 31;
    if (w >= BB * SS) return;

    const int b = w >> 12;
    const int s = w & (SS - 1);
    const float* pb = pos + (size_t)b * NN * 3;

    const float cx = g_centers[w * 3 + 0];
    const float cy = g_centers[w * 3 + 1];
    const float cz = g_centers[w * 3 + 2];
    const float R2 = (float)(0.1 * 0.1);
    const int excl = s - b * (NN - SS);

    int cnt = 0;
    for (int j0 = 0; j0 < NN && cnt < KK; j0 += 32) {
        int j = j0 + lane;
        float x_ = pb[j * 3 + 0];
        float y_ = pb[j * 3 + 1];
        float z_ = pb[j * 3 + 2];
        float dx = __fsub_rn(cx, x_);
        float dy = __fsub_rn(cy, y_);
        float dz = __fsub_rn(cz, z_);
        float d2 = __fadd_rn(__fadd_rn(__fmul_rn(dx, dx), __fmul_rn(dy, dy)),
                             __fmul_rn(dz, dz));
        bool hit = (d2 <= R2) && (j != excl);
        unsigned m = __ballot_sync(0xffffffffu, hit);
        while (m && cnt < KK) {
            int bit = __ffs(m) - 1;
            if (lane == bit) g_nbr[w * KK + cnt] = j0 + bit;
            cnt++;
            m &= m - 1;
        }
    }
    if (lane == 0) {
        g_cnt[w] = cnt;
        out_batch[w] = (float)b;
    }
}

// ===========================================================================
// Kernel 3: gather + MLP(19->64->64->128) + max over K+1 (unchanged).
// ===========================================================================
__global__ void __launch_bounds__(256, 1)
mlp_kernel(const float* __restrict__ x, const float* __restrict__ pos,
           const float* __restrict__ W1, const float* __restrict__ B1,
           const float* __restrict__ W2, const float* __restrict__ B2,
           const float* __restrict__ W3, const float* __restrict__ B3,
           float* __restrict__ out_x)
{
    extern __shared__ float sw[];
    float* sW1 = sw;
    float* sb1 = sW1 + 19 * 64;
    float* sW2 = sb1 + 64;
    float* sb2 = sW2 + 4096;
    float* sW3 = sb2 + 64;
    float* sb3 = sW3 + 8192;

    const int tid = threadIdx.x;
    for (int i = tid; i < 19 * 64; i += 256) sW1[i] = W1[i];
    for (int i = tid; i < 64;      i += 256) sb1[i] = B1[i];
    for (int i = tid; i < 64 * 64; i += 256) sW2[i] = W2[i];
    for (int i = tid; i < 64;      i += 256) sb2[i] = B2[i];
    for (int i = tid; i < 64 * 128; i += 256) sW3[i] = W3[i];
    for (int i = tid; i < 128;     i += 256) sb3[i] = B3[i];
    __syncthreads();

    const int lane = tid & 31;
    const int c    = blockIdx.x * 8 + (tid >> 5);
    const int b    = c >> 12;
    const int s    = c & (SS - 1);

    const float cx = g_centers[c * 3 + 0];
    const float cy = g_centers[c * 3 + 1];
    const float cz = g_centers[c * 3 + 2];
    const float ccomp = (lane == 16) ? cx : ((lane == 17) ? cy : cz);
    const int cnt = g_cnt[c];

    float m0 = -3.0e38f, m1 = -3.0e38f, m2 = -3.0e38f, m3 = -3.0e38f;

    auto process4 = [&](const int rows[4], int nv) {
        float fv[4];
#pragma unroll
        for (int e = 0; e < 4; e++) {
            int r = rows[e];
            float v = 0.f;
            if (lane < FIN)          v = x[(size_t)r * FIN + lane];
            else if (lane < FIN + 3) v = pos[(size_t)r * 3 + (lane - FIN)] - ccomp;
            fv[e] = (e < nv) ? v : 0.f;
        }
        float a0[4], a1[4];
#pragma unroll
        for (int e = 0; e < 4; e++) { a0[e] = sb1[lane]; a1[e] = sb1[lane + 32]; }
#pragma unroll
        for (int i = 0; i < FIN + 3; i++) {
            float w0 = sW1[i * 64 + lane];
            float w1 = sW1[i * 64 + 32 + lane];
#pragma unroll
            for (int e = 0; e < 4; e++) {
                float v = __shfl_sync(0xffffffffu, fv[e], i);
                a0[e] = fmaf(v, w0, a0[e]);
                a1[e] = fmaf(v, w1, a1[e]);
            }
        }
#pragma unroll
        for (int e = 0; e < 4; e++) { a0[e] = fmaxf(a0[e], 0.f); a1[e] = fmaxf(a1[e], 0.f); }

        float g0[4], g1[4];
#pragma unroll
        for (int e = 0; e < 4; e++) { g0[e] = sb2[lane]; g1[e] = sb2[lane + 32]; }
#pragma unroll
        for (int i = 0; i < 64; i++) {
            float w0 = sW2[i * 64 + lane];
            float w1 = sW2[i * 64 + 32 + lane];
#pragma unroll
            for (int e = 0; e < 4; e++) {
                float v = (i < 32) ? __shfl_sync(0xffffffffu, a0[e], i)
                                   : __shfl_sync(0xffffffffu, a1[e], i - 32);
                g0[e] = fmaf(v, w0, g0[e]);
                g1[e] = fmaf(v, w1, g1[e]);
            }
        }
#pragma unroll
        for (int e = 0; e < 4; e++) { g0[e] = fmaxf(g0[e], 0.f); g1[e] = fmaxf(g1[e], 0.f); }

        float h0[4], h1v[4], h2v[4], h3v[4];
#pragma unroll
        for (int e = 0; e < 4; e++) {
            h0[e]  = sb3[lane];       h1v[e] = sb3[lane + 32];
            h2v[e] = sb3[lane + 64];  h3v[e] = sb3[lane + 96];
        }
#pragma unroll
        for (int i = 0; i < 64; i++) {
            float w0 = sW3[i * 128 + lane];
            float w1 = sW3[i * 128 + 32 + lane];
            float w2 = sW3[i * 128 + 64 + lane];
            float w3 = sW3[i * 128 + 96 + lane];
#pragma unroll
            for (int e = 0; e < 4; e++) {
                float v = (i < 32) ? __shfl_sync(0xffffffffu, g0[e], i)
                                   : __shfl_sync(0xffffffffu, g1[e], i - 32);
                h0[e]  = fmaf(v, w0, h0[e]);
                h1v[e] = fmaf(v, w1, h1v[e]);
                h2v[e] = fmaf(v, w2, h2v[e]);
                h3v[e] = fmaf(v, w3, h3v[e]);
            }
        }
#pragma unroll
        for (int e = 0; e < 4; e++) {
            if (e < nv) {
                m0 = fmaxf(m0, h0[e]);  m1 = fmaxf(m1, h1v[e]);
                m2 = fmaxf(m2, h2v[e]); m3 = fmaxf(m3, h3v[e]);
            }
        }
    };

    for (int eb = 0; eb < cnt; eb += 4) {
        int nv = min(4, cnt - eb);
        int rows[4];
#pragma unroll
        for (int e = 0; e < 4; e++) {
            int kk = eb + ((e < nv) ? e : 0);
            rows[e] = b * NN + g_nbr[c * KK + kk];
        }
        process4(rows, nv);
    }
    {
        int dflat = b * SS + s;
        int rows[4] = { dflat, dflat, dflat, dflat };
        process4(rows, 1);
    }

    out_x[(size_t)c * HOUT + lane]      = m0;
    out_x[(size_t)c * HOUT + lane + 32] = m1;
    out_x[(size_t)c * HOUT + lane + 64] = m2;
    out_x[(size_t)c * HOUT + lane + 96] = m3;
}

// ===========================================================================
// launch
// ===========================================================================
extern "C" void kernel_launch(void* const* d_in, const int* in_sizes, int n_in,
                              void* d_out, int out_size)
{
    const float* x   = (const float*)d_in[0];
    const float* pos = (const float*)d_in[1];
    const float* W1 = (const float*)d_in[3];
    const float* B1 = (const float*)d_in[4];
    const float* W2 = (const float*)d_in[5];
    const float* B2 = (const float*)d_in[6];
    const float* W3 = (const float*)d_in[7];
    const float* B3 = (const float*)d_in[8];

    float* out_x = (float*)d_out;
    float* out_c = out_x + (size_t)BB * SS * HOUT;
    float* out_b = out_c + (size_t)BB * SS * 3;

    const size_t fps_smem = (size_t)3 * NN * sizeof(float);   // 192 KB
    const size_t mlp_smem = (size_t)13760 * sizeof(float);
    cudaFuncSetAttribute(fps_kernel, cudaFuncAttributeMaxDynamicSharedMemorySize, (int)fps_smem);
    cudaFuncSetAttribute(mlp_kernel, cudaFuncAttributeMaxDynamicSharedMemorySize, (int)mlp_smem);

    init_hist_kernel<<<(BB * NCELL + 255) / 256, 256>>>();
    cell_count_kernel<<<(BB * NN + 255) / 256, 256>>>(pos);
    cell_scan_kernel<<<BB, NCELL>>>();
    cell_scatter_kernel<<<(BB * NN + 255) / 256, 256>>>(pos);
    fps_kernel<<<BB, 1024, fps_smem>>>(pos, out_c);
    ballq_kernel<<<(BB * SS * 32) / 256, 256>>>(pos, out_b);
    mlp_kernel<<<(BB * SS) / 8, 256, mlp_smem>>>(x, pos, W1, B1, W2, B2, W3, B3, out_x);
}